// round 12
// baseline (speedup 1.0000x reference)
#include <cuda_runtime.h>
#include <math.h>

// Problem constants (fixed by reference setup_inputs)
#define B  4
#define T  4096
#define C  64
#define HS 64
#define BT (B * T)

#define QBLOCKS 256            // qkv blocks: 64 rows x 3 matrices each
#define ABLOCKS 484            // attn blocks: 34 rows each (484*34 >= 16384)
#define NBLOCKS (QBLOCKS + ABLOCKS)   // 740 = 5 blocks/SM x 148 SMs
#define ROWS_PER_ABLOCK 34

#define QSTR 68
#define SMEM_BYTES (2 * 64 * QSTR * 4)   // xs + ws = 34816 B

// Scratch + flag (device globals; no allocations allowed)
__device__ float g_q[BT * HS];
__device__ float g_k[BT * HS];
__device__ float g_v[BT * HS];
__device__ unsigned int g_flag;

// ---------------------------------------------------------------------------
__global__ void init_kernel() { g_flag = 0u; }

// ---------------------------------------------------------------------------
// ONE heterogeneous grid:
//   blocks [0, QBLOCKS)        : QKV projection (R8-proven 4x4 tile GEMM)
//   blocks [QBLOCKS, NBLOCKS)  : per-row zero stores, then (after flag) band
// Concurrency is guaranteed by placement: the whole grid is one wave.
// ---------------------------------------------------------------------------
__global__ __launch_bounds__(256, 5)
void mono_kernel(const float* __restrict__ x,
                 const float* __restrict__ Wq,
                 const float* __restrict__ Wk,
                 const float* __restrict__ Wv,
                 float* __restrict__ op_out,    // [B*T, 64]
                 float* __restrict__ attn_out)  // [B, T, T]
{
    extern __shared__ float sm[];
    const int bid = blockIdx.x;
    const int tid = threadIdx.x;

    if (bid < QBLOCKS) {
        // ==================== QKV blocks ====================
        float* xs = sm;               // xs[c*QSTR + m] = x[row0+m][c]
        float* ws = sm + 64 * QSTR;   // ws[c*QSTR + h] = W[h][c]
        const int row0 = bid * 64;

        #pragma unroll
        for (int idx = tid; idx < 64 * 64; idx += 256) {
            const int m = idx >> 6, c = idx & 63;
            xs[c * QSTR + m] = x[(size_t)(row0 + m) * C + c];
        }

        const float* Wm[3] = {Wq, Wk, Wv};
        float* Om[3] = {g_q, g_k, g_v};

        const int tm = (tid >> 4) * 4;
        const int tn = (tid & 15) * 4;

        #pragma unroll 1
        for (int mtx = 0; mtx < 3; ++mtx) {
            #pragma unroll
            for (int idx = tid; idx < 64 * 64; idx += 256) {
                const int h = idx >> 6, c = idx & 63;
                ws[c * QSTR + h] = Wm[mtx][idx];
            }
            __syncthreads();

            float acc[4][4];
            #pragma unroll
            for (int i = 0; i < 4; i++)
                #pragma unroll
                for (int j = 0; j < 4; j++) acc[i][j] = 0.0f;

            #pragma unroll 8
            for (int c = 0; c < 64; ++c) {
                const float4 a4 =
                    *reinterpret_cast<const float4*>(&xs[c * QSTR + tm]);
                const float4 b4 =
                    *reinterpret_cast<const float4*>(&ws[c * QSTR + tn]);
                acc[0][0] += a4.x * b4.x; acc[0][1] += a4.x * b4.y;
                acc[0][2] += a4.x * b4.z; acc[0][3] += a4.x * b4.w;
                acc[1][0] += a4.y * b4.x; acc[1][1] += a4.y * b4.y;
                acc[1][2] += a4.y * b4.z; acc[1][3] += a4.y * b4.w;
                acc[2][0] += a4.z * b4.x; acc[2][1] += a4.z * b4.y;
                acc[2][2] += a4.z * b4.z; acc[2][3] += a4.z * b4.w;
                acc[3][0] += a4.w * b4.x; acc[3][1] += a4.w * b4.y;
                acc[3][2] += a4.w * b4.z; acc[3][3] += a4.w * b4.w;
            }

            float* out = Om[mtx];
            #pragma unroll
            for (int i = 0; i < 4; i++) {
                float4 v4 = make_float4(acc[i][0], acc[i][1],
                                        acc[i][2], acc[i][3]);
                *reinterpret_cast<float4*>(
                    &out[(size_t)(row0 + tm + i) * HS + tn]) = v4;
            }
            __syncthreads();
        }

        // Publish: all q/k/v of this block written.
        __syncthreads();
        if (tid == 0) {
            __threadfence();
            atomicAdd(&g_flag, 1u);
        }
        return;
    }

    // ==================== attn blocks ====================
    const int warp = tid >> 5;
    const int lane = tid & 31;
    const int w0 = (bid - QBLOCKS) * ROWS_PER_ABLOCK;
    const int wend = min(w0 + ROWS_PER_ABLOCK, BT);
    const float4 z = make_float4(0.f, 0.f, 0.f, 0.f);

    // ---- phase A: zero stores (skipping the <=2 band float4 slots/row) ----
    for (int w = w0 + warp; w < wend; w += 8) {
        const int b = w >> 12;
        const int t = w & (T - 1);
        const int lo = max(t - 2, 0);
        const int hi = min(t + 2, T - 1);
        const int fa = lo >> 2;
        const int fb = hi >> 2;

        float4* row4 = reinterpret_cast<float4*>(
            attn_out + (size_t)b * T * T + (size_t)t * T);

        #pragma unroll 4
        for (int i4 = lane; i4 < T / 4; i4 += 32) {
            if (i4 != fa && i4 != fb) __stcs(&row4[i4], z);
        }
    }

    // ---- phase B: wait for all qkv blocks, then band + op ----
    if (lane == 0) {
        while (*(volatile unsigned int*)&g_flag < (unsigned)QBLOCKS)
            __nanosleep(128);
    }
    __syncwarp();
    __threadfence();   // acquire: order flag read before g_q/g_k/g_v reads

    for (int w = w0 + warp; w < wend; w += 8) {
        const int b = w >> 12;
        const int t = w & (T - 1);

        const float2 myq =
            reinterpret_cast<const float2*>(g_q + (size_t)w * HS)[lane];

        float score[5];
        #pragma unroll
        for (int d = 0; d < 5; ++d) {
            const int s = t - 2 + d;
            const bool valid = (unsigned)s < (unsigned)T;
            float p = 0.0f;
            if (valid) {
                const float2 kk = reinterpret_cast<const float2*>(
                    g_k + ((size_t)(b * T + s)) * HS)[lane];
                p = myq.x * kk.x + myq.y * kk.y;
            }
            #pragma unroll
            for (int off = 16; off > 0; off >>= 1)
                p += __shfl_xor_sync(0xFFFFFFFFu, p, off);
            // scale = C^-0.5 = 1/8 ; triu quirk: +1.0 when s > t (d > 2)
            score[d] = valid ? (p * 0.125f + (d > 2 ? 1.0f : 0.0f)) : -1e30f;
        }

        float m = score[0];
        #pragma unroll
        for (int d = 1; d < 5; ++d) m = fmaxf(m, score[d]);
        float p5[5], sum = 0.0f;
        #pragma unroll
        for (int d = 0; d < 5; ++d) { p5[d] = expf(score[d] - m); sum += p5[d]; }
        const float inv = 1.0f / sum;
        #pragma unroll
        for (int d = 0; d < 5; ++d) p5[d] *= inv;

        // op row: each lane owns 2 channels
        float2 acc = make_float2(0.0f, 0.0f);
        #pragma unroll
        for (int d = 0; d < 5; ++d) {
            const int s = t - 2 + d;
            if ((unsigned)s < (unsigned)T) {
                const float2 vv = reinterpret_cast<const float2*>(
                    g_v + ((size_t)(b * T + s)) * HS)[lane];
                acc.x += p5[d] * vv.x;
                acc.y += p5[d] * vv.y;
            }
        }
        reinterpret_cast<float2*>(op_out + (size_t)w * HS)[lane] = acc;

        // band float4 slots
        const int lo = max(t - 2, 0);
        const int hi = min(t + 2, T - 1);
        const int fa = lo >> 2;
        const int fb = hi >> 2;

        #define BV(s_) (((s_) >= lo && (s_) <= hi)                             \
                          ? ((s_) == t - 2 ? p5[0]                             \
                           : (s_) == t - 1 ? p5[1]                             \
                           : (s_) == t     ? p5[2]                             \
                           : (s_) == t + 1 ? p5[3] : p5[4])                    \
                          : 0.0f)
        const float4 va = make_float4(BV(4 * fa + 0), BV(4 * fa + 1),
                                      BV(4 * fa + 2), BV(4 * fa + 3));
        const float4 vb = make_float4(BV(4 * fb + 0), BV(4 * fb + 1),
                                      BV(4 * fb + 2), BV(4 * fb + 3));
        #undef BV

        float4* row4 = reinterpret_cast<float4*>(
            attn_out + (size_t)b * T * T + (size_t)t * T);
        __stcs(&row4[fa], va);
        if (fb != fa) __stcs(&row4[fb], vb);
    }
}

// ---------------------------------------------------------------------------
extern "C" void kernel_launch(void* const* d_in, const int* in_sizes, int n_in,
                              void* d_out, int out_size)
{
    const float* x  = (const float*)d_in[0];
    const float* Wq = (const float*)d_in[1];
    const float* Wk = (const float*)d_in[2];
    const float* Wv = (const float*)d_in[3];

    float* out = (float*)d_out;
    float* op_out   = out;                     // [B*T*HS]
    float* attn_out = out + (size_t)BT * HS;   // [B*T*T]

    // Reset the qkv-done flag, then run the single heterogeneous grid.
    init_kernel<<<1, 1>>>();
    mono_kernel<<<NBLOCKS, 256, SMEM_BYTES>>>(x, Wq, Wk, Wv, op_out, attn_out);
}

// round 13
// speedup vs baseline: 1.0503x; 1.0503x over previous
#include <cuda_runtime.h>
#include <math.h>

// Problem constants (fixed by reference setup_inputs)
#define B  4
#define T  4096
#define C  64
#define HS 64
#define BT (B * T)

#define RPB  8                  // attn rows per block
#define NBLK (BT / RPB)         // 2048 blocks
#define XSTR 68                 // x_s row stride (floats, mult of 4)
#define OSTR 66                 // q/k/v smem row stride (floats, mult of 2)

// ---------------------------------------------------------------------------
// ONE fused kernel. Each block is fully self-contained:
//   - loads x rows [r0-2, r0+10) (clamped) and W (from L2, 50KB/block)
//   - computes q/k/v for the 12-row halo into smem (warps 0-3)
//   - band softmax + op rows + band float4 slots (warps 0-3)
//   - zero-fills the 8 attn rows; work grabbed via smem atomic counter so
//     warps 4-7 store from t~0 and GEMM warps join when done.
// No inter-block dependencies, no global scratch, no streams.
// ---------------------------------------------------------------------------
__global__ __launch_bounds__(256, 6)
void fused_kernel(const float* __restrict__ x,
                  const float* __restrict__ Wq,
                  const float* __restrict__ Wk,
                  const float* __restrict__ Wv,
                  float* __restrict__ op_out,    // [B*T, 64]
                  float* __restrict__ attn_out)  // [B, T, T]
{
    __shared__ float W_s[64 * 64];        // rotated swizzle: [h][(c+4h)&63]
    __shared__ float x_s[12 * XSTR];      // x_s[i][c], i = local halo row
    __shared__ float qkv_s[3][12 * OSTR]; // q/k/v[i][h]
    __shared__ unsigned int s_ctr;        // store-row work counter

    const int tid  = threadIdx.x;
    const int wid  = tid >> 5;
    const int lane = tid & 31;
    const int r0   = blockIdx.x * RPB;    // global row base (block in 1 batch)
    const int bb   = r0 >> 12;            // batch
    const int t0   = r0 & (T - 1);        // row base within batch

    if (tid == 0) s_ctr = 0u;
    __syncthreads();

    if (wid < 4) {
        // ================== compute half (128 threads) ==================
        // ---- load x halo: 12 rows x 16 float4 (rows clamped to [0,BT)) ----
        #pragma unroll
        for (int idx = tid; idx < 192; idx += 128) {
            const int i = idx >> 4, c4 = idx & 15;
            const int gr = min(max(r0 - 2 + i, 0), BT - 1);
            *reinterpret_cast<float4*>(&x_s[i * XSTR + 4 * c4]) =
                *reinterpret_cast<const float4*>(&x[(size_t)gr * C + 4 * c4]);
        }

        const float* Wm[3] = {Wq, Wk, Wv};
        const int h = tid & 63;
        const int g = tid >> 6;            // 0..1

        #pragma unroll 1
        for (int m = 0; m < 3; ++m) {
            // load W rotated-swizzled: W_s[h][(c+4h)&63] = W[h][c]
            #pragma unroll
            for (int idx = tid; idx < 1024; idx += 128) {
                const int hh = idx >> 4, c4 = idx & 15;
                *reinterpret_cast<float4*>(
                    &W_s[hh * 64 + ((4 * c4 + 4 * hh) & 63)]) =
                    *reinterpret_cast<const float4*>(&Wm[m][hh * 64 + 4 * c4]);
            }
            asm volatile("bar.sync 1, 128;" ::: "memory");

            float acc[6];
            #pragma unroll
            for (int j = 0; j < 6; j++) acc[j] = 0.0f;

            #pragma unroll 4
            for (int c4 = 0; c4 < 16; ++c4) {
                const float4 wv = *reinterpret_cast<const float4*>(
                    &W_s[h * 64 + ((4 * c4 + 4 * h) & 63)]);
                #pragma unroll
                for (int j = 0; j < 6; j++) {
                    const int rm = g + 2 * j;        // halo rows 0..11
                    const float4 a4 = *reinterpret_cast<const float4*>(
                        &x_s[rm * XSTR + 4 * c4]);
                    acc[j] += a4.x * wv.x + a4.y * wv.y
                            + a4.z * wv.z + a4.w * wv.w;
                }
            }
            #pragma unroll
            for (int j = 0; j < 6; j++)
                qkv_s[m][(g + 2 * j) * OSTR + h] = acc[j];
            asm volatile("bar.sync 1, 128;" ::: "memory");
        }

        // ---- band: warp wid handles local rows 2*wid, 2*wid+1 ----
        #pragma unroll
        for (int rr = 0; rr < 2; ++rr) {
            const int lr = 2 * wid + rr;       // 0..7
            const int t = t0 + lr;
            const int w = r0 + lr;

            const float2 q2 = *reinterpret_cast<const float2*>(
                &qkv_s[0][(lr + 2) * OSTR + 2 * lane]);

            float score[5];
            #pragma unroll
            for (int d = 0; d < 5; ++d) {
                const int s = t - 2 + d;
                const bool valid = (unsigned)s < (unsigned)T;
                float p = 0.0f;
                if (valid) {
                    const float2 k2 = *reinterpret_cast<const float2*>(
                        &qkv_s[1][(lr + d) * OSTR + 2 * lane]);
                    p = q2.x * k2.x + q2.y * k2.y;
                }
                #pragma unroll
                for (int off = 16; off > 0; off >>= 1)
                    p += __shfl_xor_sync(0xFFFFFFFFu, p, off);
                // scale = C^-0.5 = 1/8 ; triu quirk: +1.0 when s > t (d > 2)
                score[d] = valid ? (p * 0.125f + (d > 2 ? 1.0f : 0.0f)) : -1e30f;
            }

            float mmax = score[0];
            #pragma unroll
            for (int d = 1; d < 5; ++d) mmax = fmaxf(mmax, score[d]);
            float p5[5], sum = 0.0f;
            #pragma unroll
            for (int d = 0; d < 5; ++d) {
                p5[d] = expf(score[d] - mmax);
                sum += p5[d];
            }
            const float inv = 1.0f / sum;
            #pragma unroll
            for (int d = 0; d < 5; ++d) p5[d] *= inv;

            // op row: each lane owns 2 channels
            float2 acc2 = make_float2(0.0f, 0.0f);
            #pragma unroll
            for (int d = 0; d < 5; ++d) {
                const int s = t - 2 + d;
                if ((unsigned)s < (unsigned)T) {
                    const float2 v2 = *reinterpret_cast<const float2*>(
                        &qkv_s[2][(lr + d) * OSTR + 2 * lane]);
                    acc2.x += p5[d] * v2.x;
                    acc2.y += p5[d] * v2.y;
                }
            }
            *reinterpret_cast<float2*>(
                &op_out[(size_t)w * HS + 2 * lane]) = acc2;

            // band float4 slots (zero stores skip these)
            const int lo = max(t - 2, 0);
            const int hi = min(t + 2, T - 1);
            const int fa = lo >> 2;
            const int fb = hi >> 2;
            #define BV(s_) (((s_) >= lo && (s_) <= hi)                        \
                              ? ((s_) == t - 2 ? p5[0]                        \
                               : (s_) == t - 1 ? p5[1]                        \
                               : (s_) == t     ? p5[2]                        \
                               : (s_) == t + 1 ? p5[3] : p5[4])               \
                              : 0.0f)
            const float4 va = make_float4(BV(4 * fa + 0), BV(4 * fa + 1),
                                          BV(4 * fa + 2), BV(4 * fa + 3));
            const float4 vb = make_float4(BV(4 * fb + 0), BV(4 * fb + 1),
                                          BV(4 * fb + 2), BV(4 * fb + 3));
            #undef BV

            float4* row4 = reinterpret_cast<float4*>(
                attn_out + (size_t)bb * T * T + (size_t)t * T);
            if (lane == 0) __stcs(&row4[fa], va);
            if (lane == 1 && fb != fa) __stcs(&row4[fb], vb);
        }
    }

    // ================== store half (ALL warps; 4-7 start at t~0) ==========
    const float4 z = make_float4(0.f, 0.f, 0.f, 0.f);
    for (;;) {
        unsigned r;
        if (lane == 0) r = atomicAdd(&s_ctr, 1u);
        r = __shfl_sync(0xFFFFFFFFu, r, 0);
        if (r >= (unsigned)RPB) break;

        const int t = t0 + (int)r;
        const int lo = max(t - 2, 0);
        const int hi = min(t + 2, T - 1);
        const int fa = lo >> 2;
        const int fb = hi >> 2;

        float4* row4 = reinterpret_cast<float4*>(
            attn_out + (size_t)bb * T * T + (size_t)t * T);

        #pragma unroll 4
        for (int i4 = lane; i4 < T / 4; i4 += 32) {
            if (i4 != fa && i4 != fb) __stcs(&row4[i4], z);
        }
    }
}

// ---------------------------------------------------------------------------
extern "C" void kernel_launch(void* const* d_in, const int* in_sizes, int n_in,
                              void* d_out, int out_size)
{
    const float* x  = (const float*)d_in[0];
    const float* Wq = (const float*)d_in[1];
    const float* Wk = (const float*)d_in[2];
    const float* Wv = (const float*)d_in[3];

    float* out = (float*)d_out;
    float* op_out   = out;                     // [B*T*HS]
    float* attn_out = out + (size_t)BT * HS;   // [B*T*T]

    fused_kernel<<<NBLK, 256>>>(x, Wq, Wk, Wv, op_out, attn_out);
}

// round 14
// speedup vs baseline: 1.3222x; 1.2588x over previous
#include <cuda_runtime.h>
#include <math.h>

// Problem constants (fixed by reference setup_inputs)
#define B  4
#define T  4096
#define C  64
#define HS 64
#define BT (B * T)

#define QGRID 768     // qkv blocks (256 x 3)
#define BGRID 2048    // band blocks

// Scratch + sync state (device globals; no allocations allowed).
// Self-resetting across launches: qkv's last block sets g_flag, band's last
// block clears it, so every graph replay starts from the same state.
__device__ float g_q[BT * HS];
__device__ float g_k[BT * HS];
__device__ float g_v[BT * HS];
__device__ unsigned int g_qkv_ctr;
__device__ unsigned int g_band_ctr;
__device__ volatile unsigned int g_flag;

#define QSTR 68

// ---------------------------------------------------------------------------
// Kernel 1: QKV projection (R8-proven). out[t][h] = sum_c x[t][c]*W[h][c]
// Grid (256,3), 256 thr, 4x4 thread tile, float4 smem loads.
// Last block to finish publishes g_flag (release).
// ---------------------------------------------------------------------------
__global__ __launch_bounds__(256, 4)
void qkv_kernel(const float* __restrict__ x,
                const float* __restrict__ Wq,
                const float* __restrict__ Wk,
                const float* __restrict__ Wv)
{
    __shared__ float xs[64 * QSTR];
    __shared__ float ws[64 * QSTR];

    const float* W;
    float* out;
    if (blockIdx.y == 0)      { W = Wq; out = g_q; }
    else if (blockIdx.y == 1) { W = Wk; out = g_k; }
    else                      { W = Wv; out = g_v; }

    const int row0 = blockIdx.x * 64;
    const int tid = threadIdx.x;

    #pragma unroll
    for (int idx = tid; idx < 64 * 64; idx += 256) {
        int h = idx >> 6, c = idx & 63;
        ws[c * QSTR + h] = W[idx];
    }
    #pragma unroll
    for (int idx = tid; idx < 64 * 64; idx += 256) {
        int m = idx >> 6, c = idx & 63;
        xs[c * QSTR + m] = x[(size_t)(row0 + m) * C + c];
    }
    __syncthreads();

    const int tm = (tid >> 4) * 4;
    const int tn = (tid & 15) * 4;

    float acc[4][4];
    #pragma unroll
    for (int i = 0; i < 4; i++)
        #pragma unroll
        for (int j = 0; j < 4; j++) acc[i][j] = 0.0f;

    #pragma unroll 8
    for (int c = 0; c < 64; ++c) {
        const float4 a4 = *reinterpret_cast<const float4*>(&xs[c * QSTR + tm]);
        const float4 b4 = *reinterpret_cast<const float4*>(&ws[c * QSTR + tn]);
        acc[0][0] += a4.x * b4.x; acc[0][1] += a4.x * b4.y;
        acc[0][2] += a4.x * b4.z; acc[0][3] += a4.x * b4.w;
        acc[1][0] += a4.y * b4.x; acc[1][1] += a4.y * b4.y;
        acc[1][2] += a4.y * b4.z; acc[1][3] += a4.y * b4.w;
        acc[2][0] += a4.z * b4.x; acc[2][1] += a4.z * b4.y;
        acc[2][2] += a4.z * b4.z; acc[2][3] += a4.z * b4.w;
        acc[3][0] += a4.w * b4.x; acc[3][1] += a4.w * b4.y;
        acc[3][2] += a4.w * b4.z; acc[3][3] += a4.w * b4.w;
    }

    #pragma unroll
    for (int i = 0; i < 4; i++) {
        float4 v4 = make_float4(acc[i][0], acc[i][1], acc[i][2], acc[i][3]);
        *reinterpret_cast<float4*>(&out[(size_t)(row0 + tm + i) * HS + tn]) = v4;
    }

    // Publish completion (release). Last block sets the flag + resets counter.
    __syncthreads();
    if (tid == 0) {
        __threadfence();
        const unsigned o = atomicAdd(&g_qkv_ctr, 1u);
        if (o == QGRID - 1) {
            g_qkv_ctr = 0u;
            g_flag = 1u;
        }
    }
}

// ---------------------------------------------------------------------------
// Kernel Z: zero-fill the attn matrix, skipping the <=2 band float4 slots per
// row. Launched with ProgrammaticStreamSerialization: queues behind qkv's
// pending blocks and backfills as they retire (no data dependency on qkv).
// ---------------------------------------------------------------------------
__global__ __launch_bounds__(256, 8)
void zero_kernel(float* __restrict__ attn_out)   // [B, T, T]
{
    const int warp_in_blk = threadIdx.x >> 5;
    const int lane = threadIdx.x & 31;
    const int w = blockIdx.x * 8 + warp_in_blk;
    const int b = w >> 12;
    const int t = w & (T - 1);

    const int lo = max(t - 2, 0);
    const int hi = min(t + 2, T - 1);
    const int fa = lo >> 2;
    const int fb = hi >> 2;

    float4* row4 = reinterpret_cast<float4*>(
        attn_out + (size_t)b * T * T + (size_t)t * T);
    const float4 z = make_float4(0.f, 0.f, 0.f, 0.f);

    #pragma unroll 4
    for (int i4 = lane; i4 < T / 4; i4 += 32) {
        if (i4 != fa && i4 != fb) __stcs(&row4[i4], z);
    }
}

// ---------------------------------------------------------------------------
// Kernel 2: band attention. PDL lets its blocks enter the dispatch queue at
// qkv completion (~18us) instead of after zero's full dispatch, so they
// backfill zero's drain. True dependency on qkv is enforced by g_flag
// (set ~18us; band blocks are placed ~35us+ -> spin cost ~0).
// ---------------------------------------------------------------------------
__global__ __launch_bounds__(256, 8)
void band_kernel(float* __restrict__ op_out,    // [B*T, 64]
                 float* __restrict__ attn_out)  // [B, T, T]
{
    const int tid = threadIdx.x;

    // Gate on qkv completion (usually already set when this block is placed).
    if (tid == 0) {
        while (g_flag == 0u) __nanosleep(64);
    }
    __syncthreads();
    __threadfence();   // acquire: order flag read before g_q/g_k/g_v reads

    const int warp_in_blk = tid >> 5;
    const int lane = tid & 31;
    const int w = blockIdx.x * 8 + warp_in_blk;
    const int b = w >> 12;
    const int t = w & (T - 1);

    const float2 myq = reinterpret_cast<const float2*>(g_q + (size_t)w * HS)[lane];

    float score[5];
    #pragma unroll
    for (int d = 0; d < 5; ++d) {
        const int s = t - 2 + d;
        const bool valid = (unsigned)s < (unsigned)T;
        float p = 0.0f;
        if (valid) {
            const float2 kk =
                reinterpret_cast<const float2*>(g_k + ((size_t)(b * T + s)) * HS)[lane];
            p = myq.x * kk.x + myq.y * kk.y;
        }
        #pragma unroll
        for (int off = 16; off > 0; off >>= 1)
            p += __shfl_xor_sync(0xFFFFFFFFu, p, off);
        // scale = C^-0.5 = 1/8 ; triu quirk: +1.0 when s > t (d > 2)
        score[d] = valid ? (p * 0.125f + (d > 2 ? 1.0f : 0.0f)) : -1e30f;
    }

    float m = score[0];
    #pragma unroll
    for (int d = 1; d < 5; ++d) m = fmaxf(m, score[d]);
    float p5[5], sum = 0.0f;
    #pragma unroll
    for (int d = 0; d < 5; ++d) { p5[d] = expf(score[d] - m); sum += p5[d]; }
    const float inv = 1.0f / sum;
    #pragma unroll
    for (int d = 0; d < 5; ++d) p5[d] *= inv;

    // op row: each lane owns 2 channels
    float2 acc = make_float2(0.0f, 0.0f);
    #pragma unroll
    for (int d = 0; d < 5; ++d) {
        const int s = t - 2 + d;
        if ((unsigned)s < (unsigned)T) {
            const float2 vv =
                reinterpret_cast<const float2*>(g_v + ((size_t)(b * T + s)) * HS)[lane];
            acc.x += p5[d] * vv.x;
            acc.y += p5[d] * vv.y;
        }
    }
    reinterpret_cast<float2*>(op_out + (size_t)w * HS)[lane] = acc;

    // band float4 slots (zero skips these; addresses disjoint)
    const int lo = max(t - 2, 0);
    const int hi = min(t + 2, T - 1);
    const int fa = lo >> 2;
    const int fb = hi >> 2;

    #define BV(s_) (((s_) >= lo && (s_) <= hi)                                   \
                      ? ((s_) == t - 2 ? p5[0]                                   \
                       : (s_) == t - 1 ? p5[1]                                   \
                       : (s_) == t     ? p5[2]                                   \
                       : (s_) == t + 1 ? p5[3] : p5[4])                          \
                      : 0.0f)
    const float4 va = make_float4(BV(4 * fa + 0), BV(4 * fa + 1),
                                  BV(4 * fa + 2), BV(4 * fa + 3));
    const float4 vb = make_float4(BV(4 * fb + 0), BV(4 * fb + 1),
                                  BV(4 * fb + 2), BV(4 * fb + 3));
    #undef BV

    float4* row4 = reinterpret_cast<float4*>(
        attn_out + (size_t)b * T * T + (size_t)t * T);
    if (lane == 0) __stcs(&row4[fa], va);
    if (lane == 1 && fb != fa) __stcs(&row4[fb], vb);

    // Self-reset: the last band block to finish clears the flag so the next
    // graph replay starts from pristine state.
    __syncthreads();
    if (tid == 0) {
        const unsigned o = atomicAdd(&g_band_ctr, 1u);
        if (o == BGRID - 1) {
            g_band_ctr = 0u;
            g_flag = 0u;
        }
    }
}

// ---------------------------------------------------------------------------
extern "C" void kernel_launch(void* const* d_in, const int* in_sizes, int n_in,
                              void* d_out, int out_size)
{
    const float* x  = (const float*)d_in[0];
    const float* Wq = (const float*)d_in[1];
    const float* Wk = (const float*)d_in[2];
    const float* Wv = (const float*)d_in[3];

    float* out = (float*)d_out;
    float* op_out   = out;                     // [B*T*HS]
    float* attn_out = out + (size_t)BT * HS;   // [B*T*T]

    // 1. qkv: normal launch.
    dim3 g1(BT / 64, 3);
    qkv_kernel<<<g1, 256>>>(x, Wq, Wk, Wv);

    // PDL attribute: allow the next kernels to launch before their stream
    // predecessor completes (we manage the only true dependency via g_flag).
    cudaLaunchAttribute attrs[1];
    attrs[0].id = cudaLaunchAttributeProgrammaticStreamSerialization;
    attrs[0].val.programmaticStreamSerializationAllowed = 1;

    // 2. zero: overlaps qkv (no data dependency; disjoint writes).
    {
        cudaLaunchConfig_t cfg = {};
        cfg.gridDim = dim3(BT / 8);
        cfg.blockDim = dim3(256);
        cfg.dynamicSmemBytes = 0;
        cfg.stream = 0;
        cfg.attrs = attrs;
        cfg.numAttrs = 1;
        cudaLaunchKernelEx(&cfg, zero_kernel, attn_out);
    }

    // 3. band: enters dispatch queue at qkv completion, backfills zero's
    //    drain; gated on g_flag for the qkv data dependency.
    {
        cudaLaunchConfig_t cfg = {};
        cfg.gridDim = dim3(BGRID);
        cfg.blockDim = dim3(256);
        cfg.dynamicSmemBytes = 0;
        cfg.stream = 0;
        cfg.attrs = attrs;
        cfg.numAttrs = 1;
        cudaLaunchKernelEx(&cfg, band_kernel, op_out, attn_out);
    }
}

// round 15
// speedup vs baseline: 1.7057x; 1.2901x over previous
#include <cuda_runtime.h>
#include <math.h>

// Problem constants (fixed by reference setup_inputs)
#define B  4
#define T  4096
#define C  64
#define HS 64
#define BT (B * T)

// Scratch for q, k, v projections (device globals; no allocations allowed)
__device__ float g_q[BT * HS];
__device__ float g_k[BT * HS];
__device__ float g_v[BT * HS];

// Streams with priorities + fork/join events, created once at init.
static cudaStream_t g_sZero;   // low priority  : bulk zero-fill
static cudaStream_t g_sComp;   // high priority : qkv -> band
static cudaEvent_t  g_evFork, g_evZ, g_evC;
namespace {
struct InitStreams {
    InitStreams() {
        int leastPrio = 0, greatestPrio = 0;
        cudaDeviceGetStreamPriorityRange(&leastPrio, &greatestPrio);
        cudaStreamCreateWithPriority(&g_sZero, cudaStreamNonBlocking, leastPrio);
        cudaStreamCreateWithPriority(&g_sComp, cudaStreamNonBlocking, greatestPrio);
        cudaEventCreateWithFlags(&g_evFork, cudaEventDisableTiming);
        cudaEventCreateWithFlags(&g_evZ, cudaEventDisableTiming);
        cudaEventCreateWithFlags(&g_evC, cudaEventDisableTiming);
    }
};
InitStreams g_initStreams;
}

typedef unsigned long long u64;
__device__ __forceinline__ u64 pack2(float a) {
    u64 r;
    asm("mov.b64 %0, {%1, %1};" : "=l"(r) : "f"(a));
    return r;
}
__device__ __forceinline__ void ffma2(u64& acc, u64 a, u64 b) {
    asm("fma.rn.f32x2 %0, %1, %2, %0;" : "+l"(acc) : "l"(a), "l"(b));
}

// ---------------------------------------------------------------------------
// Kernel Z: zero-fill the attn matrix, skipping the <=2 band float4 slots per
// row (band_kernel writes those at disjoint addresses). One warp per row.
// 0 smem, 16 regs -> backfills free warp slots alongside qkv from t~0.
// ---------------------------------------------------------------------------
__global__ __launch_bounds__(256, 8)
void zero_kernel(float* __restrict__ attn_out)   // [B, T, T]
{
    const int warp_in_blk = threadIdx.x >> 5;
    const int lane = threadIdx.x & 31;
    const int w = blockIdx.x * 8 + warp_in_blk;   // row id in [0, BT)
    const int b = w >> 12;
    const int t = w & (T - 1);

    const int lo = max(t - 2, 0);
    const int hi = min(t + 2, T - 1);
    const int fa = lo >> 2;
    const int fb = hi >> 2;

    float4* row4 = reinterpret_cast<float4*>(
        attn_out + (size_t)b * T * T + (size_t)t * T);
    const float4 z = make_float4(0.f, 0.f, 0.f, 0.f);

    #pragma unroll 4
    for (int i4 = lane; i4 < T / 4; i4 += 32) {
        if (i4 != fa && i4 != fb) __stcs(&row4[i4], z);
    }
}

// ---------------------------------------------------------------------------
// Kernel 1: QKV projection, 8x8 FFMA2 edition.
// Grid (128, 3), 128 threads/block, 51 KB dynamic smem. Each thread computes
// an 8-row x 8-col tile with packed fma.rn.f32x2 (1B smem-read/FMA, 2 FMA per
// math instr). All 384 blocks are wave-1 resident (2.6/SM, 4 warps each), so
// the zero stream starts placing blocks immediately.
// ---------------------------------------------------------------------------
#define XSTR8 132  // xs row stride (floats), mult of 4
#define WSTR8 68   // ws row stride (floats), mult of 4
#define QKV8_SMEM_BYTES ((64 * XSTR8 + 64 * WSTR8) * 4)  // 51200 B

__global__ __launch_bounds__(128)
void qkv_kernel(const float* __restrict__ x,
                const float* __restrict__ Wq,
                const float* __restrict__ Wk,
                const float* __restrict__ Wv)
{
    extern __shared__ float sm[];
    float* xs = sm;                // xs[c*XSTR8 + m] = x[row0+m][c], m in [0,128)
    float* ws = sm + 64 * XSTR8;   // ws[c*WSTR8 + h] = W[h][c]

    const int tid = threadIdx.x;

    const float* W;
    float* out;
    if (blockIdx.y == 0)      { W = Wq; out = g_q; }
    else if (blockIdx.y == 1) { W = Wk; out = g_k; }
    else                      { W = Wv; out = g_v; }

    const int row0 = blockIdx.x * 128;

    // Load x tile (128 rows x 64 cols), transposed into smem.
    #pragma unroll
    for (int idx = tid; idx < 128 * 64; idx += 128) {
        const int m = idx >> 6, c = idx & 63;
        xs[c * XSTR8 + m] = x[(size_t)(row0 + m) * C + c];
    }
    // Load W transposed: ws[c][h].
    #pragma unroll
    for (int idx = tid; idx < 64 * 64; idx += 128) {
        const int h = idx >> 6, c = idx & 63;
        ws[c * WSTR8 + h] = W[idx];
    }
    __syncthreads();

    const int tm = (tid >> 3) * 8;   // row group: 0..120 (16B-aligned)
    const int tn = (tid & 7) * 8;    // col group: 0..56  (16B-aligned)

    u64 acc[8][4];
    #pragma unroll
    for (int i = 0; i < 8; i++)
        #pragma unroll
        for (int j = 0; j < 4; j++) acc[i][j] = 0ULL;

    #pragma unroll 4
    for (int c = 0; c < 64; ++c) {
        const float* xrow = &xs[c * XSTR8 + tm];
        const float4 a0 = *reinterpret_cast<const float4*>(xrow);
        const float4 a1 = *reinterpret_cast<const float4*>(xrow + 4);

        const ulonglong2 bv0 =
            *reinterpret_cast<const ulonglong2*>(&ws[c * WSTR8 + tn]);
        const ulonglong2 bv1 =
            *reinterpret_cast<const ulonglong2*>(&ws[c * WSTR8 + tn + 4]);
        const u64 b0 = bv0.x, b1 = bv0.y, b2 = bv1.x, b3 = bv1.y;

        u64 p;
        p = pack2(a0.x);
        ffma2(acc[0][0], p, b0); ffma2(acc[0][1], p, b1);
        ffma2(acc[0][2], p, b2); ffma2(acc[0][3], p, b3);
        p = pack2(a0.y);
        ffma2(acc[1][0], p, b0); ffma2(acc[1][1], p, b1);
        ffma2(acc[1][2], p, b2); ffma2(acc[1][3], p, b3);
        p = pack2(a0.z);
        ffma2(acc[2][0], p, b0); ffma2(acc[2][1], p, b1);
        ffma2(acc[2][2], p, b2); ffma2(acc[2][3], p, b3);
        p = pack2(a0.w);
        ffma2(acc[3][0], p, b0); ffma2(acc[3][1], p, b1);
        ffma2(acc[3][2], p, b2); ffma2(acc[3][3], p, b3);
        p = pack2(a1.x);
        ffma2(acc[4][0], p, b0); ffma2(acc[4][1], p, b1);
        ffma2(acc[4][2], p, b2); ffma2(acc[4][3], p, b3);
        p = pack2(a1.y);
        ffma2(acc[5][0], p, b0); ffma2(acc[5][1], p, b1);
        ffma2(acc[5][2], p, b2); ffma2(acc[5][3], p, b3);
        p = pack2(a1.z);
        ffma2(acc[6][0], p, b0); ffma2(acc[6][1], p, b1);
        ffma2(acc[6][2], p, b2); ffma2(acc[6][3], p, b3);
        p = pack2(a1.w);
        ffma2(acc[7][0], p, b0); ffma2(acc[7][1], p, b1);
        ffma2(acc[7][2], p, b2); ffma2(acc[7][3], p, b3);
    }

    // Store 8 rows x 8 cols (two 16B stores per row).
    #pragma unroll
    for (int i = 0; i < 8; i++) {
        u64* o = reinterpret_cast<u64*>(
            &out[(size_t)(row0 + tm + i) * HS + tn]);
        ulonglong2 v0; v0.x = acc[i][0]; v0.y = acc[i][1];
        ulonglong2 v1; v1.x = acc[i][2]; v1.y = acc[i][3];
        *reinterpret_cast<ulonglong2*>(o)     = v0;
        *reinterpret_cast<ulonglong2*>(o + 2) = v1;
    }
}

// ---------------------------------------------------------------------------
// Kernel 2: band attention. One warp per (b, t) row: 5 dots, softmax, op row,
// and ONLY the <=2 band float4 slots of the attn row (zeros done elsewhere at
// disjoint addresses, no ordering needed).
// ---------------------------------------------------------------------------
__global__ __launch_bounds__(256, 8)
void band_kernel(float* __restrict__ op_out,    // [B*T, 64]
                 float* __restrict__ attn_out)  // [B, T, T]
{
    const int warp_in_blk = threadIdx.x >> 5;
    const int lane = threadIdx.x & 31;
    const int w = blockIdx.x * 8 + warp_in_blk;
    const int b = w >> 12;
    const int t = w & (T - 1);

    const float2 myq = reinterpret_cast<const float2*>(g_q + (size_t)w * HS)[lane];

    float score[5];
    #pragma unroll
    for (int d = 0; d < 5; ++d) {
        const int s = t - 2 + d;
        const bool valid = (unsigned)s < (unsigned)T;
        float p = 0.0f;
        if (valid) {
            const float2 kk =
                reinterpret_cast<const float2*>(g_k + ((size_t)(b * T + s)) * HS)[lane];
            p = myq.x * kk.x + myq.y * kk.y;
        }
        #pragma unroll
        for (int off = 16; off > 0; off >>= 1)
            p += __shfl_xor_sync(0xFFFFFFFFu, p, off);
        // scale = C^-0.5 = 1/8 ; triu quirk: +1.0 when s > t (d > 2)
        score[d] = valid ? (p * 0.125f + (d > 2 ? 1.0f : 0.0f)) : -1e30f;
    }

    float m = score[0];
    #pragma unroll
    for (int d = 1; d < 5; ++d) m = fmaxf(m, score[d]);
    float p5[5], sum = 0.0f;
    #pragma unroll
    for (int d = 0; d < 5; ++d) { p5[d] = expf(score[d] - m); sum += p5[d]; }
    const float inv = 1.0f / sum;
    #pragma unroll
    for (int d = 0; d < 5; ++d) p5[d] *= inv;

    // op row: each lane owns 2 channels
    float2 acc = make_float2(0.0f, 0.0f);
    #pragma unroll
    for (int d = 0; d < 5; ++d) {
        const int s = t - 2 + d;
        if ((unsigned)s < (unsigned)T) {
            const float2 vv =
                reinterpret_cast<const float2*>(g_v + ((size_t)(b * T + s)) * HS)[lane];
            acc.x += p5[d] * vv.x;
            acc.y += p5[d] * vv.y;
        }
    }
    reinterpret_cast<float2*>(op_out + (size_t)w * HS)[lane] = acc;

    // band float4 slots
    const int lo = max(t - 2, 0);
    const int hi = min(t + 2, T - 1);
    const int fa = lo >> 2;
    const int fb = hi >> 2;

    #define BV(s_) (((s_) >= lo && (s_) <= hi)                                   \
                      ? ((s_) == t - 2 ? p5[0]                                   \
                       : (s_) == t - 1 ? p5[1]                                   \
                       : (s_) == t     ? p5[2]                                   \
                       : (s_) == t + 1 ? p5[3] : p5[4])                          \
                      : 0.0f)
    const float4 va = make_float4(BV(4 * fa + 0), BV(4 * fa + 1),
                                  BV(4 * fa + 2), BV(4 * fa + 3));
    const float4 vb = make_float4(BV(4 * fb + 0), BV(4 * fb + 1),
                                  BV(4 * fb + 2), BV(4 * fb + 3));
    #undef BV

    float4* row4 = reinterpret_cast<float4*>(
        attn_out + (size_t)b * T * T + (size_t)t * T);
    if (lane == 0) __stcs(&row4[fa], va);
    if (lane == 1 && fb != fa) __stcs(&row4[fb], vb);
}

// ---------------------------------------------------------------------------
extern "C" void kernel_launch(void* const* d_in, const int* in_sizes, int n_in,
                              void* d_out, int out_size)
{
    const float* x  = (const float*)d_in[0];
    const float* Wq = (const float*)d_in[1];
    const float* Wk = (const float*)d_in[2];
    const float* Wv = (const float*)d_in[3];

    float* out = (float*)d_out;
    float* op_out   = out;                     // [B*T*HS]
    float* attn_out = out + (size_t)BT * HS;   // [B*T*T]

    cudaFuncSetAttribute(qkv_kernel,
                         cudaFuncAttributeMaxDynamicSharedMemorySize,
                         QKV8_SMEM_BYTES);

    // Fork from the capture stream into both priority streams.
    cudaEventRecord(g_evFork, 0);
    cudaStreamWaitEvent(g_sComp, g_evFork, 0);
    cudaStreamWaitEvent(g_sZero, g_evFork, 0);

    // R8-proven FIFO, now with a wave-1-resident qkv (384 blocks, 2.6/SM,
    // 4 warps each): zero's 0-smem blocks start placing immediately and
    // keep ~50 warp slots/SM storing; band backfills zero's retire-drain.
    dim3 g1(BT / 128, 3);
    qkv_kernel<<<g1, 128, QKV8_SMEM_BYTES, g_sComp>>>(x, Wq, Wk, Wv);

    zero_kernel<<<BT / 8, 256, 0, g_sZero>>>(attn_out);

    band_kernel<<<BT / 8, 256, 0, g_sComp>>>(op_out, attn_out);

    // Join both streams back into the capture stream.
    cudaEventRecord(g_evZ, g_sZero);
    cudaStreamWaitEvent(0, g_evZ, 0);
    cudaEventRecord(g_evC, g_sComp);
    cudaStreamWaitEvent(0, g_evC, 0);
}

// round 16
// speedup vs baseline: 1.7728x; 1.0393x over previous
#include <cuda_runtime.h>
#include <math.h>

// Problem constants (fixed by reference setup_inputs)
#define B  4
#define T  4096
#define C  64
#define HS 64
#define BT (B * T)

// Scratch for q, k, v projections (device globals; no allocations allowed)
__device__ float g_q[BT * HS];
__device__ float g_k[BT * HS];
__device__ float g_v[BT * HS];

// Streams with priorities + fork/join events, created once at init.
static cudaStream_t g_sZero;   // low priority  : bulk zero-fill
static cudaStream_t g_sComp;   // high priority : qkv -> band
static cudaEvent_t  g_evFork, g_evZ, g_evC;
namespace {
struct InitStreams {
    InitStreams() {
        int leastPrio = 0, greatestPrio = 0;
        cudaDeviceGetStreamPriorityRange(&leastPrio, &greatestPrio);
        cudaStreamCreateWithPriority(&g_sZero, cudaStreamNonBlocking, leastPrio);
        cudaStreamCreateWithPriority(&g_sComp, cudaStreamNonBlocking, greatestPrio);
        cudaEventCreateWithFlags(&g_evFork, cudaEventDisableTiming);
        cudaEventCreateWithFlags(&g_evZ, cudaEventDisableTiming);
        cudaEventCreateWithFlags(&g_evC, cudaEventDisableTiming);
    }
};
InitStreams g_initStreams;
}

typedef unsigned long long u64;
__device__ __forceinline__ u64 pack2(float a) {
    u64 r;
    asm("mov.b64 %0, {%1, %1};" : "=l"(r) : "f"(a));
    return r;
}
__device__ __forceinline__ void ffma2(u64& acc, u64 a, u64 b) {
    asm("fma.rn.f32x2 %0, %1, %2, %0;" : "+l"(acc) : "l"(a), "l"(b));
}

// ---------------------------------------------------------------------------
// Kernel Z: zero-fill the attn matrix, skipping the <=2 band float4 slots per
// row (band_kernel writes those at disjoint addresses). One warp per row.
// 0 smem, 16 regs -> backfills free warp slots alongside qkv from t~0.
// ---------------------------------------------------------------------------
__global__ __launch_bounds__(256, 8)
void zero_kernel(float* __restrict__ attn_out)   // [B, T, T]
{
    const int warp_in_blk = threadIdx.x >> 5;
    const int lane = threadIdx.x & 31;
    const int w = blockIdx.x * 8 + warp_in_blk;   // row id in [0, BT)
    const int b = w >> 12;
    const int t = w & (T - 1);

    const int lo = max(t - 2, 0);
    const int hi = min(t + 2, T - 1);
    const int fa = lo >> 2;
    const int fb = hi >> 2;

    float4* row4 = reinterpret_cast<float4*>(
        attn_out + (size_t)b * T * T + (size_t)t * T);
    const float4 z = make_float4(0.f, 0.f, 0.f, 0.f);

    #pragma unroll 4
    for (int i4 = lane; i4 < T / 4; i4 += 32) {
        if (i4 != fa && i4 != fb) __stcs(&row4[i4], z);
    }
}

// ---------------------------------------------------------------------------
// Kernel 1: QKV projection, 8x4 FFMA2 edition with 256 threads/block.
// Grid (128, 3), 51 KB dynamic smem. Each thread computes an 8-row x 4-col
// tile with packed fma.rn.f32x2. vs R15: same math density but 2x the warps
// per block (8 vs 4) -> ~21 warps/SM for latency hiding, ~70 regs.
// All 384 blocks wave-1 resident; zero stream places immediately.
// ---------------------------------------------------------------------------
#define XSTR8 132  // xs row stride (floats), mult of 4
#define WSTR8 68   // ws row stride (floats), mult of 4
#define QKV8_SMEM_BYTES ((64 * XSTR8 + 64 * WSTR8) * 4)  // 51200 B

__global__ __launch_bounds__(256)
void qkv_kernel(const float* __restrict__ x,
                const float* __restrict__ Wq,
                const float* __restrict__ Wk,
                const float* __restrict__ Wv)
{
    extern __shared__ float sm[];
    float* xs = sm;                // xs[c*XSTR8 + m] = x[row0+m][c], m in [0,128)
    float* ws = sm + 64 * XSTR8;   // ws[c*WSTR8 + h] = W[h][c]

    const int tid = threadIdx.x;

    const float* W;
    float* out;
    if (blockIdx.y == 0)      { W = Wq; out = g_q; }
    else if (blockIdx.y == 1) { W = Wk; out = g_k; }
    else                      { W = Wv; out = g_v; }

    const int row0 = blockIdx.x * 128;

    // Load x tile (128 rows x 64 cols), transposed into smem.
    #pragma unroll
    for (int idx = tid; idx < 128 * 64; idx += 256) {
        const int m = idx >> 6, c = idx & 63;
        xs[c * XSTR8 + m] = x[(size_t)(row0 + m) * C + c];
    }
    // Load W transposed: ws[c][h].
    #pragma unroll
    for (int idx = tid; idx < 64 * 64; idx += 256) {
        const int h = idx >> 6, c = idx & 63;
        ws[c * WSTR8 + h] = W[idx];
    }
    __syncthreads();

    const int tm = (tid >> 4) * 8;   // row group: 0..120 (16 groups of 8)
    const int tn = (tid & 15) * 4;   // col group: 0..60  (16 groups of 4)

    u64 acc[8][2];
    #pragma unroll
    for (int i = 0; i < 8; i++) { acc[i][0] = 0ULL; acc[i][1] = 0ULL; }

    #pragma unroll 4
    for (int c = 0; c < 64; ++c) {
        const float* xrow = &xs[c * XSTR8 + tm];
        const float4 a0 = *reinterpret_cast<const float4*>(xrow);
        const float4 a1 = *reinterpret_cast<const float4*>(xrow + 4);

        const ulonglong2 bv =
            *reinterpret_cast<const ulonglong2*>(&ws[c * WSTR8 + tn]);
        const u64 b0 = bv.x, b1 = bv.y;

        u64 p;
        p = pack2(a0.x); ffma2(acc[0][0], p, b0); ffma2(acc[0][1], p, b1);
        p = pack2(a0.y); ffma2(acc[1][0], p, b0); ffma2(acc[1][1], p, b1);
        p = pack2(a0.z); ffma2(acc[2][0], p, b0); ffma2(acc[2][1], p, b1);
        p = pack2(a0.w); ffma2(acc[3][0], p, b0); ffma2(acc[3][1], p, b1);
        p = pack2(a1.x); ffma2(acc[4][0], p, b0); ffma2(acc[4][1], p, b1);
        p = pack2(a1.y); ffma2(acc[5][0], p, b0); ffma2(acc[5][1], p, b1);
        p = pack2(a1.z); ffma2(acc[6][0], p, b0); ffma2(acc[6][1], p, b1);
        p = pack2(a1.w); ffma2(acc[7][0], p, b0); ffma2(acc[7][1], p, b1);
    }

    // Store 8 rows x 4 cols (one 16B store per row).
    #pragma unroll
    for (int i = 0; i < 8; i++) {
        ulonglong2 v; v.x = acc[i][0]; v.y = acc[i][1];
        *reinterpret_cast<ulonglong2*>(
            &out[(size_t)(row0 + tm + i) * HS + tn]) = v;
    }
}

// ---------------------------------------------------------------------------
// Kernel 2: band attention. One warp per (b, t) row: 5 dots, softmax, op row,
// and ONLY the <=2 band float4 slots of the attn row (zeros done elsewhere at
// disjoint addresses, no ordering needed).
// ---------------------------------------------------------------------------
__global__ __launch_bounds__(256, 8)
void band_kernel(float* __restrict__ op_out,    // [B*T, 64]
                 float* __restrict__ attn_out)  // [B, T, T]
{
    const int warp_in_blk = threadIdx.x >> 5;
    const int lane = threadIdx.x & 31;
    const int w = blockIdx.x * 8 + warp_in_blk;
    const int b = w >> 12;
    const int t = w & (T - 1);

    const float2 myq = reinterpret_cast<const float2*>(g_q + (size_t)w * HS)[lane];

    float score[5];
    #pragma unroll
    for (int d = 0; d < 5; ++d) {
        const int s = t - 2 + d;
        const bool valid = (unsigned)s < (unsigned)T;
        float p = 0.0f;
        if (valid) {
            const float2 kk =
                reinterpret_cast<const float2*>(g_k + ((size_t)(b * T + s)) * HS)[lane];
            p = myq.x * kk.x + myq.y * kk.y;
        }
        #pragma unroll
        for (int off = 16; off > 0; off >>= 1)
            p += __shfl_xor_sync(0xFFFFFFFFu, p, off);
        // scale = C^-0.5 = 1/8 ; triu quirk: +1.0 when s > t (d > 2)
        score[d] = valid ? (p * 0.125f + (d > 2 ? 1.0f : 0.0f)) : -1e30f;
    }

    float m = score[0];
    #pragma unroll
    for (int d = 1; d < 5; ++d) m = fmaxf(m, score[d]);
    float p5[5], sum = 0.0f;
    #pragma unroll
    for (int d = 0; d < 5; ++d) { p5[d] = expf(score[d] - m); sum += p5[d]; }
    const float inv = 1.0f / sum;
    #pragma unroll
    for (int d = 0; d < 5; ++d) p5[d] *= inv;

    // op row: each lane owns 2 channels
    float2 acc = make_float2(0.0f, 0.0f);
    #pragma unroll
    for (int d = 0; d < 5; ++d) {
        const int s = t - 2 + d;
        if ((unsigned)s < (unsigned)T) {
            const float2 vv =
                reinterpret_cast<const float2*>(g_v + ((size_t)(b * T + s)) * HS)[lane];
            acc.x += p5[d] * vv.x;
            acc.y += p5[d] * vv.y;
        }
    }
    reinterpret_cast<float2*>(op_out + (size_t)w * HS)[lane] = acc;

    // band float4 slots
    const int lo = max(t - 2, 0);
    const int hi = min(t + 2, T - 1);
    const int fa = lo >> 2;
    const int fb = hi >> 2;

    #define BV(s_) (((s_) >= lo && (s_) <= hi)                                   \
                      ? ((s_) == t - 2 ? p5[0]                                   \
                       : (s_) == t - 1 ? p5[1]                                   \
                       : (s_) == t     ? p5[2]                                   \
                       : (s_) == t + 1 ? p5[3] : p5[4])                          \
                      : 0.0f)
    const float4 va = make_float4(BV(4 * fa + 0), BV(4 * fa + 1),
                                  BV(4 * fa + 2), BV(4 * fa + 3));
    const float4 vb = make_float4(BV(4 * fb + 0), BV(4 * fb + 1),
                                  BV(4 * fb + 2), BV(4 * fb + 3));
    #undef BV

    float4* row4 = reinterpret_cast<float4*>(
        attn_out + (size_t)b * T * T + (size_t)t * T);
    if (lane == 0) __stcs(&row4[fa], va);
    if (lane == 1 && fb != fa) __stcs(&row4[fb], vb);
}

// ---------------------------------------------------------------------------
extern "C" void kernel_launch(void* const* d_in, const int* in_sizes, int n_in,
                              void* d_out, int out_size)
{
    const float* x  = (const float*)d_in[0];
    const float* Wq = (const float*)d_in[1];
    const float* Wk = (const float*)d_in[2];
    const float* Wv = (const float*)d_in[3];

    float* out = (float*)d_out;
    float* op_out   = out;                     // [B*T*HS]
    float* attn_out = out + (size_t)BT * HS;   // [B*T*T]

    cudaFuncSetAttribute(qkv_kernel,
                         cudaFuncAttributeMaxDynamicSharedMemorySize,
                         QKV8_SMEM_BYTES);

    // Fork from the capture stream into both priority streams.
    cudaEventRecord(g_evFork, 0);
    cudaStreamWaitEvent(g_sComp, g_evFork, 0);
    cudaStreamWaitEvent(g_sZero, g_evFork, 0);

    // R15-proven FIFO with wave-1-resident qkv: zero's 0-smem blocks start
    // placing immediately; band backfills zero's retire-drain.
    dim3 g1(BT / 128, 3);
    qkv_kernel<<<g1, 256, QKV8_SMEM_BYTES, g_sComp>>>(x, Wq, Wk, Wv);

    zero_kernel<<<BT / 8, 256, 0, g_sZero>>>(attn_out);

    band_kernel<<<BT / 8, 256, 0, g_sComp>>>(op_out, attn_out);

    // Join both streams back into the capture stream.
    cudaEventRecord(g_evZ, g_sZero);
    cudaStreamWaitEvent(0, g_evZ, 0);
    cudaEventRecord(g_evC, g_sComp);
    cudaStreamWaitEvent(0, g_evC, 0);
}